// round 2
// baseline (speedup 1.0000x reference)
#include <cuda_runtime.h>

#define NB   64
#define NT   512
#define NIN  256
#define NH   512
#define NOUT 256

// ---- static device scratch (no runtime allocation) --------------------------
__device__ float g_xp[NB * NT * NH];
__device__ float g_out0[NB * NT * NH];
__device__ float g_h[2][NB][NH];
__device__ unsigned g_gen = 0;
__device__ unsigned g_cnt = 0;

// ---- recurrence config ------------------------------------------------------
#define G_B 16
#define G_J 8
#define NCTA (G_B * G_J)       // 128 CTAs, 1/SM (smem-forced) -> all co-resident
#define CTA_B 4
#define CTA_J 64
#define RTHREADS 256

#define WT_FLOATS (NH * CTA_J)            // 32768 floats = 128 KB
#define HP01_OFS  WT_FLOATS
#define HP23_OFS  (HP01_OFS + 2 * NH)
#define RED_OFS   (HP23_OFS + 2 * NH)
#define RED_PITCH 260
#define RNN_SMEM_FLOATS (RED_OFS + 32 * RED_PITCH)
#define RNN_SMEM_BYTES  (RNN_SMEM_FLOATS * 4)     // 172544 B

__device__ __forceinline__ int swzw(int w) { return w ^ (((w >> 5) & 7) << 2); }

__device__ __forceinline__ void grid_barrier() {
    __threadfence();
    __syncthreads();
    if (threadIdx.x == 0) {
        volatile unsigned* vgen = (volatile unsigned*)&g_gen;
        unsigned gen = *vgen;
        unsigned arr = atomicAdd(&g_cnt, 1u);
        if (arr == NCTA - 1) {
            g_cnt = 0;
            __threadfence();
            atomicAdd(&g_gen, 1u);
        } else {
            while (*vgen == gen) { }
        }
        __threadfence();
    }
    __syncthreads();
}

// h_new[b][j] = tanh( xp[b][t][j] + sum_k h[b][k]*Whh[j][k] )
__global__ void __launch_bounds__(RTHREADS, 1)
rnn_kernel(const float* __restrict__ xp, const float* __restrict__ Whh,
           float* __restrict__ outseq, int store_out)
{
    extern __shared__ float smem[];
    float*  Wt   = smem;
    float2* hp01 = (float2*)(smem + HP01_OFS);
    float2* hp23 = (float2*)(smem + HP23_OFS);
    float*  redf = smem + RED_OFS;

    const int tid    = threadIdx.x;
    const int gb     = blockIdx.x / G_J;
    const int gj     = blockIdx.x % G_J;
    const int b_base = gb * CTA_B;
    const int j_base = gj * CTA_J;

    // W slice, transposed: Wt[k*64 + r] = Whh[(j_base+r)*NH + k]
    for (int idx = tid; idx < CTA_J * NH; idx += RTHREADS) {
        int r = idx & (CTA_J - 1);
        int k = idx >> 6;
        Wt[k * CTA_J + r] = Whh[(j_base + r) * NH + k];
    }
    __syncthreads();

    const int jg = tid & 7;
    const int kg = tid >> 3;
    const int k0 = kg * 16;

    for (int t = 0; t < NT; ++t) {
        const int cur = t & 1, nxt = cur ^ 1;

        if (t == 0) {
            for (int idx = tid; idx < NH; idx += RTHREADS) {
                hp01[idx] = make_float2(0.f, 0.f);
                hp23[idx] = make_float2(0.f, 0.f);
            }
        } else {
            for (int idx = tid; idx < NH; idx += RTHREADS) {
                hp01[idx] = make_float2(g_h[cur][b_base + 0][idx], g_h[cur][b_base + 1][idx]);
                hp23[idx] = make_float2(g_h[cur][b_base + 2][idx], g_h[cur][b_base + 3][idx]);
            }
        }
        __syncthreads();

        float2 a01[8], a23[8];
        #pragma unroll
        for (int i = 0; i < 8; i++) { a01[i] = make_float2(0.f,0.f); a23[i] = make_float2(0.f,0.f); }

        #pragma unroll 4
        for (int kk = 0; kk < 16; ++kk) {
            const int k = k0 + kk;
            const float2 h01 = hp01[k];
            const float2 h23 = hp23[k];
            const float4 w0 = *(const float4*)(Wt + k * CTA_J + jg * 4);
            const float4 w1 = *(const float4*)(Wt + k * CTA_J + 32 + jg * 4);
            const float w[8] = {w0.x, w0.y, w0.z, w0.w, w1.x, w1.y, w1.z, w1.w};
            #pragma unroll
            for (int i = 0; i < 8; i++) {
                a01[i].x += w[i] * h01.x;  a01[i].y += w[i] * h01.y;
                a23[i].x += w[i] * h23.x;  a23[i].y += w[i] * h23.y;
            }
        }

        #pragma unroll
        for (int i = 0; i < 8; i++) {
            const int jl  = (i < 4) ? (jg * 4 + i) : (32 + jg * 4 + (i - 4));
            const int wi0 = jl * 4;
            *(float2*)(redf + kg * RED_PITCH + swzw(wi0))     = a01[i];
            *(float2*)(redf + kg * RED_PITCH + swzw(wi0 + 2)) = a23[i];
        }
        __syncthreads();

        if (tid < 128) {
            float2 s = make_float2(0.f, 0.f);
            #pragma unroll
            for (int g2 = 0; g2 < 32; ++g2) {
                const float2 v = *(const float2*)(redf + g2 * RED_PITCH + swzw(tid * 2));
                s.x += v.x;  s.y += v.y;
            }
            const int j     = tid >> 1;
            const int pr    = tid & 1;
            const int jglob = j_base + j;
            const int b0    = b_base + pr * 2;
            const int row0  = (b0 * NT + t) * NH + jglob;
            const int row1  = ((b0 + 1) * NT + t) * NH + jglob;
            const float h0 = tanhf(s.x + xp[row0]);
            const float h1 = tanhf(s.y + xp[row1]);
            g_h[nxt][b0][jglob]     = h0;
            g_h[nxt][b0 + 1][jglob] = h1;
            if (store_out) { outseq[row0] = h0; outseq[row1] = h1; }
        }

        grid_barrier();
    }
}

// ---- tiled fp32 GEMM: C[M,N] = A[M,K] @ B[N,K]^T + bias1 (+ bias2) ----------
#define BM 64
#define BN 64
#define BK 16

__global__ void __launch_bounds__(256)
gemm_nt_bias(const float* __restrict__ A, const float* __restrict__ B,
             const float* __restrict__ bias1, const float* __restrict__ bias2,
             float* __restrict__ C, int M, int N, int K)
{
    __shared__ __align__(16) float As[BK][BM];
    __shared__ __align__(16) float Bs[BK][BN];

    const int tid = threadIdx.x;
    const int m0 = blockIdx.x * BM;
    const int n0 = blockIdx.y * BN;
    const int tx = tid & 15;
    const int ty = tid >> 4;
    const int lr = tid >> 2;
    const int lc = tid & 3;

    float acc[4][4];
    #pragma unroll
    for (int i = 0; i < 4; i++)
        #pragma unroll
        for (int j = 0; j < 4; j++) acc[i][j] = 0.f;

    for (int kk0 = 0; kk0 < K; kk0 += BK) {
        const float4 av = *(const float4*)(A + (m0 + lr) * K + kk0 + lc * 4);
        const float4 bv = *(const float4*)(B + (n0 + lr) * K + kk0 + lc * 4);
        __syncthreads();
        As[lc*4+0][lr] = av.x; As[lc*4+1][lr] = av.y;
        As[lc*4+2][lr] = av.z; As[lc*4+3][lr] = av.w;
        Bs[lc*4+0][lr] = bv.x; Bs[lc*4+1][lr] = bv.y;
        Bs[lc*4+2][lr] = bv.z; Bs[lc*4+3][lr] = bv.w;
        __syncthreads();

        #pragma unroll
        for (int k = 0; k < BK; ++k) {
            const float4 a = *(const float4*)(&As[k][ty * 4]);
            const float4 b = *(const float4*)(&Bs[k][tx * 4]);
            const float avv[4] = {a.x, a.y, a.z, a.w};
            const float bvv[4] = {b.x, b.y, b.z, b.w};
            #pragma unroll
            for (int i = 0; i < 4; i++)
                #pragma unroll
                for (int j = 0; j < 4; j++)
                    acc[i][j] += avv[i] * bvv[j];
        }
    }

    #pragma unroll
    for (int i = 0; i < 4; i++) {
        const int m = m0 + ty * 4 + i;
        const int n = n0 + tx * 4;
        float bsv[4];
        #pragma unroll
        for (int j = 0; j < 4; j++) {
            bsv[j] = bias1 ? bias1[n + j] : 0.f;
            if (bias2) bsv[j] += bias2[n + j];
        }
        float4 o;
        o.x = acc[i][0] + bsv[0];
        o.y = acc[i][1] + bsv[1];
        o.z = acc[i][2] + bsv[2];
        o.w = acc[i][3] + bsv[3];
        *(float4*)(C + m * N + n) = o;
    }
}

// ---- launch -----------------------------------------------------------------
extern "C" void kernel_launch(void* const* d_in, const int* in_sizes, int n_in,
                              void* d_out, int out_size)
{
    const float* x     = (const float*)d_in[0];
    const float* W_ih0 = (const float*)d_in[1];
    const float* W_hh0 = (const float*)d_in[2];
    const float* b_ih0 = (const float*)d_in[3];
    const float* b_hh0 = (const float*)d_in[4];
    const float* W_ih1 = (const float*)d_in[5];
    const float* W_hh1 = (const float*)d_in[6];
    const float* b_ih1 = (const float*)d_in[7];
    const float* b_hh1 = (const float*)d_in[8];
    const float* W_out = (const float*)d_in[9];
    const float* b_out = (const float*)d_in[10];
    float* out = (float*)d_out;

    float *xp, *out0, *hbuf;
    cudaGetSymbolAddress((void**)&xp,   g_xp);
    cudaGetSymbolAddress((void**)&out0, g_out0);
    cudaGetSymbolAddress((void**)&hbuf, g_h);

    cudaFuncSetAttribute(rnn_kernel, cudaFuncAttributeMaxDynamicSharedMemorySize,
                         RNN_SMEM_BYTES);

    const int M = NB * NT;  // 32768

    // xp0 = x @ W_ih0^T + b_ih0 + b_hh0
    {
        dim3 grid(M / BM, NH / BN);
        gemm_nt_bias<<<grid, 256>>>(x, W_ih0, b_ih0, b_hh0, xp, M, NH, NIN);
    }
    // layer 0 recurrence (stores full sequence)
    rnn_kernel<<<NCTA, RTHREADS, RNN_SMEM_BYTES>>>(xp, W_hh0, out0, 1);

    // xp1 = out0 @ W_ih1^T + b_ih1 + b_hh1
    {
        dim3 grid(M / BM, NH / BN);
        gemm_nt_bias<<<grid, 256>>>(out0, W_ih1, b_ih1, b_hh1, xp, M, NH, NH);
    }
    // layer 1 recurrence (only final hidden needed); final state lands in g_h[0]
    rnn_kernel<<<NCTA, RTHREADS, RNN_SMEM_BYTES>>>(xp, W_hh1, nullptr, 0);

    // out = h_last @ W_out^T + b_out   (h_last = g_h[0], [64, 512])
    {
        dim3 grid(NB / BM, NOUT / BN);
        gemm_nt_bias<<<grid, 256>>>(hbuf, W_out, b_out, nullptr, out, NB, NOUT, NH);
    }
}

// round 3
// speedup vs baseline: 1.5494x; 1.5494x over previous
#include <cuda_runtime.h>

#define NB   64
#define NT   512
#define NIN  256
#define NH   512
#define NOUT 256

// ---- static device scratch (no runtime allocation) --------------------------
__device__ float g_xp[NB * NT * NH];
__device__ float g_out0[NB * NT * NH];
__device__ float g_h[2][NB][NH];
// per-batch-group barriers, 128B apart to avoid L2 line sharing
__device__ unsigned g_ggen[16 * 32];
__device__ unsigned g_gcnt[16 * 32];

// ---- recurrence config ------------------------------------------------------
#define G_B 16
#define G_J 8
#define NCTA (G_B * G_J)       // 128 CTAs, 1/SM (smem-forced) -> all co-resident
#define CTA_B 4
#define CTA_J 64
#define RTHREADS 256

#define WT_FLOATS (NH * CTA_J)            // 32768 floats = 128 KB
#define HP01_OFS  WT_FLOATS
#define HP23_OFS  (HP01_OFS + 2 * NH)
#define RED_OFS   (HP23_OFS + 2 * NH)
#define RED_PITCH 260
#define RNN_SMEM_FLOATS (RED_OFS + 32 * RED_PITCH)
#define RNN_SMEM_BYTES  (RNN_SMEM_FLOATS * 4)     // 172544 B

__device__ __forceinline__ int swzw(int w) { return w ^ (((w >> 5) & 7) << 2); }

// Barrier among the 8 CTAs of one batch group. The final __threadfence()
// (gpu scope) emits CCTL.IVALL -> flushes L1D, so subsequent g_h loads see
// the peer CTAs' L2 data. Do not weaken it.
__device__ __forceinline__ void group_barrier(int gb) {
    __threadfence();
    __syncthreads();
    if (threadIdx.x == 0) {
        unsigned* gen_p = &g_ggen[gb * 32];
        unsigned* cnt_p = &g_gcnt[gb * 32];
        volatile unsigned* vgen = (volatile unsigned*)gen_p;
        unsigned gen = *vgen;
        if (atomicAdd(cnt_p, 1u) == G_J - 1) {
            *cnt_p = 0;
            __threadfence();
            atomicAdd(gen_p, 1u);
        } else {
            while (*vgen == gen) { }
        }
        __threadfence();
    }
    __syncthreads();
}

// h_new[b][j] = tanh( xp[b][t][j] + sum_k h[b][k]*Whh[j][k] )
__global__ void __launch_bounds__(RTHREADS, 1)
rnn_kernel(const float* __restrict__ xp, const float* __restrict__ Whh,
           float* __restrict__ outseq, int store_out)
{
    extern __shared__ float smem[];
    float*  Wt   = smem;
    float2* hp01 = (float2*)(smem + HP01_OFS);
    float2* hp23 = (float2*)(smem + HP23_OFS);
    float*  redf = smem + RED_OFS;

    const int tid    = threadIdx.x;
    const int gb     = blockIdx.x / G_J;
    const int gj     = blockIdx.x % G_J;
    const int b_base = gb * CTA_B;
    const int j_base = gj * CTA_J;

    // W slice, transposed: Wt[k*64 + r] = Whh[(j_base+r)*NH + k]
    for (int idx = tid; idx < CTA_J * NH; idx += RTHREADS) {
        int r = idx & (CTA_J - 1);
        int k = idx >> 6;
        Wt[k * CTA_J + r] = Whh[(j_base + r) * NH + k];
    }
    __syncthreads();

    const int jg = tid & 7;
    const int kg = tid >> 3;
    const int k0 = kg * 16;

    // per-thread output indices for the reduction phase (tid < 128)
    const int rj    = tid >> 1;
    const int rpr   = tid & 1;
    const int rjglb = j_base + rj;
    const int rb0   = b_base + rpr * 2;

    for (int t = 0; t < NT; ++t) {
        const int cur = t & 1, nxt = cur ^ 1;

        // prefetch xp for this step early (independent of the barrier/h)
        float xpv0 = 0.f, xpv1 = 0.f;
        int row0 = 0, row1 = 0;
        if (tid < 128) {
            row0 = (rb0 * NT + t) * NH + rjglb;
            row1 = ((rb0 + 1) * NT + t) * NH + rjglb;
            xpv0 = __ldg(xp + row0);
            xpv1 = __ldg(xp + row1);
        }

        // stage h into SMEM as batch-pairs
        if (t == 0) {
            for (int idx = tid; idx < NH; idx += RTHREADS) {
                hp01[idx] = make_float2(0.f, 0.f);
                hp23[idx] = make_float2(0.f, 0.f);
            }
        } else {
            for (int idx = tid; idx < NH; idx += RTHREADS) {
                hp01[idx] = make_float2(g_h[cur][b_base + 0][idx], g_h[cur][b_base + 1][idx]);
                hp23[idx] = make_float2(g_h[cur][b_base + 2][idx], g_h[cur][b_base + 3][idx]);
            }
        }
        __syncthreads();

        // partial GEMM: 8 j x 4 b over 16 k per thread
        float2 a01[8], a23[8];
        #pragma unroll
        for (int i = 0; i < 8; i++) { a01[i] = make_float2(0.f,0.f); a23[i] = make_float2(0.f,0.f); }

        #pragma unroll 4
        for (int kk = 0; kk < 16; ++kk) {
            const int k = k0 + kk;
            const float2 h01 = hp01[k];
            const float2 h23 = hp23[k];
            const float4 w0 = *(const float4*)(Wt + k * CTA_J + jg * 4);
            const float4 w1 = *(const float4*)(Wt + k * CTA_J + 32 + jg * 4);
            const float w[8] = {w0.x, w0.y, w0.z, w0.w, w1.x, w1.y, w1.z, w1.w};
            #pragma unroll
            for (int i = 0; i < 8; i++) {
                a01[i].x += w[i] * h01.x;  a01[i].y += w[i] * h01.y;
                a23[i].x += w[i] * h23.x;  a23[i].y += w[i] * h23.y;
            }
        }

        // partials -> swizzled SMEM
        #pragma unroll
        for (int i = 0; i < 8; i++) {
            const int jl  = (i < 4) ? (jg * 4 + i) : (32 + jg * 4 + (i - 4));
            const int wi0 = jl * 4;
            *(float2*)(redf + kg * RED_PITCH + swzw(wi0))     = a01[i];
            *(float2*)(redf + kg * RED_PITCH + swzw(wi0 + 2)) = a23[i];
        }
        __syncthreads();

        // reduce over 32 k-groups, add xp, tanh, publish
        if (tid < 128) {
            float2 s0 = make_float2(0.f, 0.f);
            float2 s1 = make_float2(0.f, 0.f);
            #pragma unroll
            for (int g2 = 0; g2 < 32; g2 += 2) {
                const float2 v0 = *(const float2*)(redf + g2 * RED_PITCH + swzw(tid * 2));
                const float2 v1 = *(const float2*)(redf + (g2 + 1) * RED_PITCH + swzw(tid * 2));
                s0.x += v0.x;  s0.y += v0.y;
                s1.x += v1.x;  s1.y += v1.y;
            }
            const float h0 = tanhf(s0.x + s1.x + xpv0);
            const float h1 = tanhf(s0.y + s1.y + xpv1);
            g_h[nxt][rb0][rjglb]     = h0;
            g_h[nxt][rb0 + 1][rjglb] = h1;
            if (store_out) { outseq[row0] = h0; outseq[row1] = h1; }
        }

        group_barrier(gb);
    }
}

// ---- big tiled fp32 GEMM: C[M,N] = A[M,K] @ B[N,K]^T + bias1 (+bias2) -------
// 128x64 tile, 256 threads, 8x4 micro-tile.
#define GBM 128
#define GBN 64
#define GBK 16

__global__ void __launch_bounds__(256)
gemm128_nt_bias(const float* __restrict__ A, const float* __restrict__ B,
                const float* __restrict__ bias1, const float* __restrict__ bias2,
                float* __restrict__ C, int M, int N, int K)
{
    __shared__ __align__(16) float As[GBK][GBM];   // 8 KB
    __shared__ __align__(16) float Bs[GBK][GBN];   // 4 KB

    const int tid = threadIdx.x;
    const int m0 = blockIdx.x * GBM;
    const int n0 = blockIdx.y * GBN;
    const int tx = tid & 15;        // n micro (4 cols)
    const int ty = tid >> 4;        // m micro (8 rows)
    const int lrA = tid >> 1, lcA = tid & 1;   // A: 128 rows x 2 half-rows of 8
    const int lrB = tid >> 2, lcB = tid & 3;   // B: 64 rows x 4 float4

    float acc[8][4];
    #pragma unroll
    for (int i = 0; i < 8; i++)
        #pragma unroll
        for (int j = 0; j < 4; j++) acc[i][j] = 0.f;

    for (int kk0 = 0; kk0 < K; kk0 += GBK) {
        const float4 av0 = *(const float4*)(A + (m0 + lrA) * K + kk0 + lcA * 8);
        const float4 av1 = *(const float4*)(A + (m0 + lrA) * K + kk0 + lcA * 8 + 4);
        const float4 bv  = *(const float4*)(B + (n0 + lrB) * K + kk0 + lcB * 4);
        __syncthreads();
        As[lcA*8+0][lrA] = av0.x; As[lcA*8+1][lrA] = av0.y;
        As[lcA*8+2][lrA] = av0.z; As[lcA*8+3][lrA] = av0.w;
        As[lcA*8+4][lrA] = av1.x; As[lcA*8+5][lrA] = av1.y;
        As[lcA*8+6][lrA] = av1.z; As[lcA*8+7][lrA] = av1.w;
        Bs[lcB*4+0][lrB] = bv.x;  Bs[lcB*4+1][lrB] = bv.y;
        Bs[lcB*4+2][lrB] = bv.z;  Bs[lcB*4+3][lrB] = bv.w;
        __syncthreads();

        #pragma unroll
        for (int k = 0; k < GBK; ++k) {
            const float4 a0 = *(const float4*)(&As[k][ty * 8]);
            const float4 a1 = *(const float4*)(&As[k][ty * 8 + 4]);
            const float4 b  = *(const float4*)(&Bs[k][tx * 4]);
            const float avv[8] = {a0.x, a0.y, a0.z, a0.w, a1.x, a1.y, a1.z, a1.w};
            const float bvv[4] = {b.x, b.y, b.z, b.w};
            #pragma unroll
            for (int i = 0; i < 8; i++)
                #pragma unroll
                for (int j = 0; j < 4; j++)
                    acc[i][j] += avv[i] * bvv[j];
        }
    }

    float bsv[4];
    #pragma unroll
    for (int j = 0; j < 4; j++) {
        bsv[j] = bias1 ? bias1[n0 + tx * 4 + j] : 0.f;
        if (bias2) bsv[j] += bias2[n0 + tx * 4 + j];
    }
    #pragma unroll
    for (int i = 0; i < 8; i++) {
        const int m = m0 + ty * 8 + i;
        float4 o;
        o.x = acc[i][0] + bsv[0];
        o.y = acc[i][1] + bsv[1];
        o.z = acc[i][2] + bsv[2];
        o.w = acc[i][3] + bsv[3];
        *(float4*)(C + m * N + n0 + tx * 4) = o;
    }
}

// ---- small GEMM (64x64 tile) for the final projection (M=64) ----------------
#define BM 64
#define BN 64
#define BK 16

__global__ void __launch_bounds__(256)
gemm_nt_bias(const float* __restrict__ A, const float* __restrict__ B,
             const float* __restrict__ bias1, const float* __restrict__ bias2,
             float* __restrict__ C, int M, int N, int K)
{
    __shared__ __align__(16) float As[BK][BM];
    __shared__ __align__(16) float Bs[BK][BN];

    const int tid = threadIdx.x;
    const int m0 = blockIdx.x * BM;
    const int n0 = blockIdx.y * BN;
    const int tx = tid & 15;
    const int ty = tid >> 4;
    const int lr = tid >> 2;
    const int lc = tid & 3;

    float acc[4][4];
    #pragma unroll
    for (int i = 0; i < 4; i++)
        #pragma unroll
        for (int j = 0; j < 4; j++) acc[i][j] = 0.f;

    for (int kk0 = 0; kk0 < K; kk0 += BK) {
        const float4 av = *(const float4*)(A + (m0 + lr) * K + kk0 + lc * 4);
        const float4 bv = *(const float4*)(B + (n0 + lr) * K + kk0 + lc * 4);
        __syncthreads();
        As[lc*4+0][lr] = av.x; As[lc*4+1][lr] = av.y;
        As[lc*4+2][lr] = av.z; As[lc*4+3][lr] = av.w;
        Bs[lc*4+0][lr] = bv.x; Bs[lc*4+1][lr] = bv.y;
        Bs[lc*4+2][lr] = bv.z; Bs[lc*4+3][lr] = bv.w;
        __syncthreads();

        #pragma unroll
        for (int k = 0; k < BK; ++k) {
            const float4 a = *(const float4*)(&As[k][ty * 4]);
            const float4 b = *(const float4*)(&Bs[k][tx * 4]);
            const float avv[4] = {a.x, a.y, a.z, a.w};
            const float bvv[4] = {b.x, b.y, b.z, b.w};
            #pragma unroll
            for (int i = 0; i < 4; i++)
                #pragma unroll
                for (int j = 0; j < 4; j++)
                    acc[i][j] += avv[i] * bvv[j];
        }
    }

    #pragma unroll
    for (int i = 0; i < 4; i++) {
        const int m = m0 + ty * 4 + i;
        const int n = n0 + tx * 4;
        float bsv[4];
        #pragma unroll
        for (int j = 0; j < 4; j++) {
            bsv[j] = bias1 ? bias1[n + j] : 0.f;
            if (bias2) bsv[j] += bias2[n + j];
        }
        float4 o;
        o.x = acc[i][0] + bsv[0];
        o.y = acc[i][1] + bsv[1];
        o.z = acc[i][2] + bsv[2];
        o.w = acc[i][3] + bsv[3];
        *(float4*)(C + m * N + n) = o;
    }
}

// ---- launch -----------------------------------------------------------------
extern "C" void kernel_launch(void* const* d_in, const int* in_sizes, int n_in,
                              void* d_out, int out_size)
{
    const float* x     = (const float*)d_in[0];
    const float* W_ih0 = (const float*)d_in[1];
    const float* W_hh0 = (const float*)d_in[2];
    const float* b_ih0 = (const float*)d_in[3];
    const float* b_hh0 = (const float*)d_in[4];
    const float* W_ih1 = (const float*)d_in[5];
    const float* W_hh1 = (const float*)d_in[6];
    const float* b_ih1 = (const float*)d_in[7];
    const float* b_hh1 = (const float*)d_in[8];
    const float* W_out = (const float*)d_in[9];
    const float* b_out = (const float*)d_in[10];
    float* out = (float*)d_out;

    float *xp, *out0, *hbuf;
    cudaGetSymbolAddress((void**)&xp,   g_xp);
    cudaGetSymbolAddress((void**)&out0, g_out0);
    cudaGetSymbolAddress((void**)&hbuf, g_h);

    cudaFuncSetAttribute(rnn_kernel, cudaFuncAttributeMaxDynamicSharedMemorySize,
                         RNN_SMEM_BYTES);

    const int M = NB * NT;  // 32768

    // xp0 = x @ W_ih0^T + b_ih0 + b_hh0
    {
        dim3 grid(M / GBM, NH / GBN);
        gemm128_nt_bias<<<grid, 256>>>(x, W_ih0, b_ih0, b_hh0, xp, M, NH, NIN);
    }
    // layer 0 recurrence (stores full sequence)
    rnn_kernel<<<NCTA, RTHREADS, RNN_SMEM_BYTES>>>(xp, W_hh0, out0, 1);

    // xp1 = out0 @ W_ih1^T + b_ih1 + b_hh1
    {
        dim3 grid(M / GBM, NH / GBN);
        gemm128_nt_bias<<<grid, 256>>>(out0, W_ih1, b_ih1, b_hh1, xp, M, NH, NH);
    }
    // layer 1 recurrence (only final hidden needed); final state lands in g_h[0]
    rnn_kernel<<<NCTA, RTHREADS, RNN_SMEM_BYTES>>>(xp, W_hh1, nullptr, 0);

    // out = h_last @ W_out^T + b_out   (h_last = g_h[0], [64, 512])
    {
        dim3 grid(NB / BM, NOUT / BN);
        gemm_nt_bias<<<grid, 256>>>(hbuf, W_out, b_out, nullptr, out, NB, NOUT, NH);
    }
}